// round 1
// baseline (speedup 1.0000x reference)
#include <cuda_runtime.h>
#include <cstdint>

#define NX 8192
#define NF 8192
#define F_SIZE 512
#define OUT_SIZE 256
#define D_ATT 128
#define N_GRAPHS 16

// ---------------- scratch (no allocs allowed) ----------------
__device__ float g_query[NX * D_ATT];      // 4 MB
__device__ float g_key[NF * D_ATT];        // 4 MB
__device__ float g_value[NF * OUT_SIZE];   // 8 MB
__device__ float g_rowmax[NX];
__device__ int   g_foff[N_GRAPHS + 1];

// ---------------- graph offsets: lower_bound over sorted f_batch ----------------
__global__ void offsets_kernel(const int* __restrict__ f_batch) {
    int g = threadIdx.x;
    if (g > N_GRAPHS) return;
    int lo = 0, hi = NF;
    while (lo < hi) {
        int mid = (lo + hi) >> 1;
        if (f_batch[mid] < g) lo = mid + 1; else hi = mid;
    }
    g_foff[g] = lo;
}

#define FMA16(acc, a, b) do { \
    acc[0][0] += a.x * b.x; acc[0][1] += a.x * b.y; acc[0][2] += a.x * b.z; acc[0][3] += a.x * b.w; \
    acc[1][0] += a.y * b.x; acc[1][1] += a.y * b.y; acc[1][2] += a.y * b.z; acc[1][3] += a.y * b.w; \
    acc[2][0] += a.z * b.x; acc[2][1] += a.z * b.y; acc[2][2] += a.z * b.z; acc[2][3] += a.z * b.w; \
    acc[3][0] += a.w * b.x; acc[3][1] += a.w * b.y; acc[3][2] += a.w * b.z; acc[3][3] += a.w * b.w; \
} while (0)

__device__ __forceinline__ float* dst_select(int which) {
    return which == 0 ? g_query : (which == 1 ? g_key : g_value);
}

// ---------------- generic SGEMM: C[M,N] = A[M,K] * B[K,N], row-major ----------------
// grid: (N/64, M/64), 256 threads, 64x64 tile, 4x4 micro-tile, BK=16
__global__ __launch_bounds__(256) void sgemm64(
    const float* __restrict__ A, const float* __restrict__ B,
    int which, int N, int K)
{
    __shared__ float As[16][64];   // transposed: As[k][m]
    __shared__ float Bs[16][64];

    float* C = dst_select(which);

    const int t = threadIdx.x;
    const int m0 = blockIdx.y * 64;
    const int n0 = blockIdx.x * 64;
    const int tx = t & 15, ty = t >> 4;

    const int arow = t >> 2, acol4 = (t & 3) * 4;   // A tile 64x16
    const int brow = t >> 4, bcol4 = (t & 15) * 4;  // B tile 16x64

    float acc[4][4] = {};

    for (int k0 = 0; k0 < K; k0 += 16) {
        float4 av = *(const float4*)(A + (size_t)(m0 + arow) * K + k0 + acol4);
        As[acol4 + 0][arow] = av.x;
        As[acol4 + 1][arow] = av.y;
        As[acol4 + 2][arow] = av.z;
        As[acol4 + 3][arow] = av.w;
        *(float4*)&Bs[brow][bcol4] = *(const float4*)(B + (size_t)(k0 + brow) * N + n0 + bcol4);
        __syncthreads();
#pragma unroll
        for (int k = 0; k < 16; k++) {
            float4 a = *(const float4*)&As[k][ty * 4];
            float4 b = *(const float4*)&Bs[k][tx * 4];
            FMA16(acc, a, b);
        }
        __syncthreads();
    }
#pragma unroll
    for (int i = 0; i < 4; i++) {
        float4 v = make_float4(acc[i][0], acc[i][1], acc[i][2], acc[i][3]);
        *(float4*)(C + (size_t)(m0 + ty * 4 + i) * N + n0 + tx * 4) = v;
    }
}

// ---------------- block-diagonal scores: attn[i,j] = q[i]·k[j] for j in row's graph ----------------
// grid: NX/64, 256 threads. Q tile resident in smem; K d-tiled.
__global__ __launch_bounds__(256) void scores_kernel(
    const int* __restrict__ x_batch, float* __restrict__ attn)
{
    __shared__ float Qs[D_ATT][64];   // Qs[d][r], 32 KB
    __shared__ float Ks[16][64];      // Ks[d][c]
    __shared__ int sfs[64], sfe[64];
    __shared__ int sjmin, sjmax;

    const int t = threadIdx.x;
    const int r0 = blockIdx.x * 64;
    const int tx = t & 15, ty = t >> 4;

    if (t < 64) {
        int g = x_batch[r0 + t];
        sfs[t] = g_foff[g];
        sfe[t] = g_foff[g + 1];
    }
    __syncthreads();
    if (t == 0) {
        // x_batch sorted -> min graph at row r0, max at r0+63
        sjmin = sfs[0];
        sjmax = sfe[63];
    }

    // load Q tile (transpose-scatter)
    {
        int r = t >> 2;
        int dbase = (t & 3) * 32;
        const float* qp = g_query + (size_t)(r0 + r) * D_ATT + dbase;
#pragma unroll
        for (int it = 0; it < 8; it++) {
            float4 v = *(const float4*)(qp + it * 4);
            int d = dbase + it * 4;
            Qs[d + 0][r] = v.x;
            Qs[d + 1][r] = v.y;
            Qs[d + 2][r] = v.z;
            Qs[d + 3][r] = v.w;
        }
    }
    __syncthreads();

    const int jmin = sjmin, jmax = sjmax;
    int fs0[4], fe0[4];
#pragma unroll
    for (int i = 0; i < 4; i++) {
        fs0[i] = sfs[ty * 4 + i];
        fe0[i] = sfe[ty * 4 + i];
    }

    float rmax[4] = {-3.0e38f, -3.0e38f, -3.0e38f, -3.0e38f};

    for (int j0 = (jmin & ~63); j0 < jmax; j0 += 64) {
        float acc[4][4] = {};
        for (int d0 = 0; d0 < D_ATT; d0 += 16) {
            {
                int c = t >> 2;
                int d4 = (t & 3) * 4;
                float4 v = *(const float4*)(g_key + (size_t)(j0 + c) * D_ATT + d0 + d4);
                Ks[d4 + 0][c] = v.x;
                Ks[d4 + 1][c] = v.y;
                Ks[d4 + 2][c] = v.z;
                Ks[d4 + 3][c] = v.w;
            }
            __syncthreads();
#pragma unroll
            for (int k = 0; k < 16; k++) {
                float4 a = *(const float4*)&Qs[d0 + k][ty * 4];
                float4 b = *(const float4*)&Ks[k][tx * 4];
                FMA16(acc, a, b);
            }
            __syncthreads();
        }
        // epilogue: write valid entries, track row max
#pragma unroll
        for (int i = 0; i < 4; i++) {
            float* arow_p = attn + (size_t)(r0 + ty * 4 + i) * NF;
#pragma unroll
            for (int jj = 0; jj < 4; jj++) {
                int j = j0 + tx * 4 + jj;
                if (j >= fs0[i] && j < fe0[i]) {
                    arow_p[j] = acc[i][jj];
                    rmax[i] = fmaxf(rmax[i], acc[i][jj]);
                }
            }
        }
    }

    // reduce row max across the 16 tx lanes (same ty -> consecutive lanes)
#pragma unroll
    for (int s = 1; s < 16; s <<= 1) {
#pragma unroll
        for (int i = 0; i < 4; i++)
            rmax[i] = fmaxf(rmax[i], __shfl_xor_sync(0xffffffffu, rmax[i], s));
    }
    if (tx == 0) {
#pragma unroll
        for (int i = 0; i < 4; i++)
            g_rowmax[r0 + ty * 4 + i] = rmax[i];
    }
}

// ---------------- per-row softmax normalize in place ----------------
__global__ __launch_bounds__(128) void softmax_kernel(
    float* __restrict__ attn, const int* __restrict__ x_batch)
{
    const int i = blockIdx.x;
    const int g = x_batch[i];
    const int fs = g_foff[g], fe = g_foff[g + 1];
    const float m = g_rowmax[i];
    float* row = attn + (size_t)i * NF;
    const int t = threadIdx.x;

    float s = 0.f;
    for (int j = fs + t; j < fe; j += 128) s += expf(row[j] - m);

    __shared__ float red[4];
#pragma unroll
    for (int o = 16; o; o >>= 1) s += __shfl_xor_sync(0xffffffffu, s, o);
    if ((t & 31) == 0) red[t >> 5] = s;
    __syncthreads();
    float tot = red[0] + red[1] + red[2] + red[3];
    float inv = 1.f / tot;

    for (int j = fs + t; j < fe; j += 128) row[j] = expf(row[j] - m) * inv;
}

// ---------------- context = attn(block) @ value(block) ----------------
// grid: (OUT_SIZE/64, NX/64), 256 threads
__global__ __launch_bounds__(256) void context_kernel(
    const float* __restrict__ attn, float* __restrict__ ctx,
    const int* __restrict__ x_batch)
{
    __shared__ float As[16][64];   // As[k][r] = attn[r][k]
    __shared__ float Bs[16][64];   // Bs[k][n] = value[k][n]
    __shared__ int sjmin, sjmax;

    const int t = threadIdx.x;
    const int r0 = blockIdx.y * 64;
    const int n0 = blockIdx.x * 64;
    const int tx = t & 15, ty = t >> 4;

    if (t == 0) {
        int g0 = x_batch[r0], g1 = x_batch[r0 + 63];
        sjmin = g_foff[g0];
        sjmax = g_foff[g1 + 1];
    }
    __syncthreads();

    const int kmin = sjmin & ~15, kmax = sjmax;
    const int arow = t >> 2, acol4 = (t & 3) * 4;
    const int brow = t >> 4, bcol4 = (t & 15) * 4;

    float acc[4][4] = {};

    for (int k0 = kmin; k0 < kmax; k0 += 16) {
        // attn outside [fs,fe) per row is exactly 0 (memset), so no masking needed
        float4 av = *(const float4*)(attn + (size_t)(r0 + arow) * NF + k0 + acol4);
        As[acol4 + 0][arow] = av.x;
        As[acol4 + 1][arow] = av.y;
        As[acol4 + 2][arow] = av.z;
        As[acol4 + 3][arow] = av.w;
        *(float4*)&Bs[brow][bcol4] =
            *(const float4*)(g_value + (size_t)(k0 + brow) * OUT_SIZE + n0 + bcol4);
        __syncthreads();
#pragma unroll
        for (int k = 0; k < 16; k++) {
            float4 a = *(const float4*)&As[k][ty * 4];
            float4 b = *(const float4*)&Bs[k][tx * 4];
            FMA16(acc, a, b);
        }
        __syncthreads();
    }
#pragma unroll
    for (int i = 0; i < 4; i++) {
        float4 v = make_float4(acc[i][0], acc[i][1], acc[i][2], acc[i][3]);
        *(float4*)(ctx + (size_t)(r0 + ty * 4 + i) * OUT_SIZE + n0 + tx * 4) = v;
    }
}

// ---------------- launch ----------------
extern "C" void kernel_launch(void* const* d_in, const int* in_sizes, int n_in,
                              void* d_out, int out_size)
{
    const float* f       = (const float*)d_in[0];
    const float* h       = (const float*)d_in[2];
    const int*   f_batch = (const int*)  d_in[5];
    const int*   x_batch = (const int*)  d_in[6];
    const float* W_h     = (const float*)d_in[8];
    const float* W_key   = (const float*)d_in[9];
    const float* W_value = (const float*)d_in[10];

    float* out  = (float*)d_out;
    float* ctx  = out;                            // [NX, OUT_SIZE]
    float* attn = out + (size_t)NX * OUT_SIZE;    // [NX, NF]

    offsets_kernel<<<1, 32>>>(f_batch);

    // query = h @ W_h        [8192,256]x[256,128]
    sgemm64<<<dim3(D_ATT / 64, NX / 64), 256>>>(h, W_h, 0, D_ATT, OUT_SIZE);
    // key = f @ W_key        [8192,512]x[512,128]
    sgemm64<<<dim3(D_ATT / 64, NF / 64), 256>>>(f, W_key, 1, D_ATT, F_SIZE);
    // value = f @ W_value    [8192,512]x[512,256]
    sgemm64<<<dim3(OUT_SIZE / 64, NF / 64), 256>>>(f, W_value, 2, OUT_SIZE, F_SIZE);

    // zero the full attn output (masked entries are exactly 0 in fp32 softmax)
    cudaMemsetAsync(attn, 0, (size_t)NX * NF * sizeof(float), 0);

    scores_kernel<<<NX / 64, 256>>>(x_batch, attn);
    softmax_kernel<<<NX, 128>>>(attn, x_batch);
    context_kernel<<<dim3(OUT_SIZE / 64, NX / 64), 256>>>(attn, ctx, x_batch);
}

// round 2
// speedup vs baseline: 1.0012x; 1.0012x over previous
#include <cuda_runtime.h>
#include <cstdint>

#define NX 8192
#define NF 8192
#define F_SIZE 512
#define OUT_SIZE 256
#define D_ATT 128
#define N_GRAPHS 16

// ---------------- scratch (no allocs allowed) ----------------
__device__ float g_query[NX * D_ATT];      // 4 MB
__device__ float g_key[NF * D_ATT];        // 4 MB
__device__ float g_value[NF * OUT_SIZE];   // 8 MB
__device__ float g_rowmax[NX];
__device__ int   g_foff[N_GRAPHS + 1];

// ---------------- graph offsets: lower_bound over sorted f_batch ----------------
__global__ void offsets_kernel(const int* __restrict__ f_batch) {
    int g = threadIdx.x;
    if (g > N_GRAPHS) return;
    int lo = 0, hi = NF;
    while (lo < hi) {
        int mid = (lo + hi) >> 1;
        if (f_batch[mid] < g) lo = mid + 1; else hi = mid;
    }
    g_foff[g] = lo;
}

#define FMA16(acc, a, b) do { \
    acc[0][0] += a.x * b.x; acc[0][1] += a.x * b.y; acc[0][2] += a.x * b.z; acc[0][3] += a.x * b.w; \
    acc[1][0] += a.y * b.x; acc[1][1] += a.y * b.y; acc[1][2] += a.y * b.z; acc[1][3] += a.y * b.w; \
    acc[2][0] += a.z * b.x; acc[2][1] += a.z * b.y; acc[2][2] += a.z * b.z; acc[2][3] += a.z * b.w; \
    acc[3][0] += a.w * b.x; acc[3][1] += a.w * b.y; acc[3][2] += a.w * b.z; acc[3][3] += a.w * b.w; \
} while (0)

__device__ __forceinline__ float* dst_select(int which) {
    return which == 0 ? g_query : (which == 1 ? g_key : g_value);
}

// ---------------- generic SGEMM: C[M,N] = A[M,K] * B[K,N], row-major ----------------
// grid: (N/64, M/64), 256 threads, 64x64 tile, 4x4 micro-tile, BK=16
__global__ __launch_bounds__(256) void sgemm64(
    const float* __restrict__ A, const float* __restrict__ B,
    int which, int N, int K)
{
    __shared__ float As[16][64];   // transposed: As[k][m]
    __shared__ float Bs[16][64];

    float* C = dst_select(which);

    const int t = threadIdx.x;
    const int m0 = blockIdx.y * 64;
    const int n0 = blockIdx.x * 64;
    const int tx = t & 15, ty = t >> 4;

    const int arow = t >> 2, acol4 = (t & 3) * 4;   // A tile 64x16
    const int brow = t >> 4, bcol4 = (t & 15) * 4;  // B tile 16x64

    float acc[4][4] = {};

    for (int k0 = 0; k0 < K; k0 += 16) {
        float4 av = *(const float4*)(A + (size_t)(m0 + arow) * K + k0 + acol4);
        As[acol4 + 0][arow] = av.x;
        As[acol4 + 1][arow] = av.y;
        As[acol4 + 2][arow] = av.z;
        As[acol4 + 3][arow] = av.w;
        *(float4*)&Bs[brow][bcol4] = *(const float4*)(B + (size_t)(k0 + brow) * N + n0 + bcol4);
        __syncthreads();
#pragma unroll
        for (int k = 0; k < 16; k++) {
            float4 a = *(const float4*)&As[k][ty * 4];
            float4 b = *(const float4*)&Bs[k][tx * 4];
            FMA16(acc, a, b);
        }
        __syncthreads();
    }
#pragma unroll
    for (int i = 0; i < 4; i++) {
        float4 v = make_float4(acc[i][0], acc[i][1], acc[i][2], acc[i][3]);
        *(float4*)(C + (size_t)(m0 + ty * 4 + i) * N + n0 + tx * 4) = v;
    }
}

// ---------------- block-diagonal scores: attn[i,j] = q[i]·k[j] for j in row's graph ----------------
// grid: NX/64, 256 threads. Q tile resident in smem; K d-tiled.
__global__ __launch_bounds__(256) void scores_kernel(
    const int* __restrict__ x_batch, float* __restrict__ attn)
{
    __shared__ float Qs[D_ATT][64];   // Qs[d][r], 32 KB
    __shared__ float Ks[16][64];      // Ks[d][c]
    __shared__ int sfs[64], sfe[64];
    __shared__ int sjmin, sjmax;

    const int t = threadIdx.x;
    const int r0 = blockIdx.x * 64;
    const int tx = t & 15, ty = t >> 4;

    if (t < 64) {
        int g = x_batch[r0 + t];
        sfs[t] = g_foff[g];
        sfe[t] = g_foff[g + 1];
    }
    __syncthreads();
    if (t == 0) {
        // x_batch sorted -> min graph at row r0, max at r0+63
        sjmin = sfs[0];
        sjmax = sfe[63];
    }

    // load Q tile (transpose-scatter)
    {
        int r = t >> 2;
        int dbase = (t & 3) * 32;
        const float* qp = g_query + (size_t)(r0 + r) * D_ATT + dbase;
#pragma unroll
        for (int it = 0; it < 8; it++) {
            float4 v = *(const float4*)(qp + it * 4);
            int d = dbase + it * 4;
            Qs[d + 0][r] = v.x;
            Qs[d + 1][r] = v.y;
            Qs[d + 2][r] = v.z;
            Qs[d + 3][r] = v.w;
        }
    }
    __syncthreads();

    const int jmin = sjmin, jmax = sjmax;
    int fs0[4], fe0[4];
#pragma unroll
    for (int i = 0; i < 4; i++) {
        fs0[i] = sfs[ty * 4 + i];
        fe0[i] = sfe[ty * 4 + i];
    }

    float rmax[4] = {-3.0e38f, -3.0e38f, -3.0e38f, -3.0e38f};

    for (int j0 = (jmin & ~63); j0 < jmax; j0 += 64) {
        float acc[4][4] = {};
        for (int d0 = 0; d0 < D_ATT; d0 += 16) {
            {
                int c = t >> 2;
                int d4 = (t & 3) * 4;
                float4 v = *(const float4*)(g_key + (size_t)(j0 + c) * D_ATT + d0 + d4);
                Ks[d4 + 0][c] = v.x;
                Ks[d4 + 1][c] = v.y;
                Ks[d4 + 2][c] = v.z;
                Ks[d4 + 3][c] = v.w;
            }
            __syncthreads();
#pragma unroll
            for (int k = 0; k < 16; k++) {
                float4 a = *(const float4*)&Qs[d0 + k][ty * 4];
                float4 b = *(const float4*)&Ks[k][tx * 4];
                FMA16(acc, a, b);
            }
            __syncthreads();
        }
        // epilogue: write valid entries, track row max
#pragma unroll
        for (int i = 0; i < 4; i++) {
            float* arow_p = attn + (size_t)(r0 + ty * 4 + i) * NF;
#pragma unroll
            for (int jj = 0; jj < 4; jj++) {
                int j = j0 + tx * 4 + jj;
                if (j >= fs0[i] && j < fe0[i]) {
                    arow_p[j] = acc[i][jj];
                    rmax[i] = fmaxf(rmax[i], acc[i][jj]);
                }
            }
        }
    }

    // reduce row max across the 16 tx lanes (same ty -> consecutive lanes)
#pragma unroll
    for (int s = 1; s < 16; s <<= 1) {
#pragma unroll
        for (int i = 0; i < 4; i++)
            rmax[i] = fmaxf(rmax[i], __shfl_xor_sync(0xffffffffu, rmax[i], s));
    }
    if (tx == 0) {
#pragma unroll
        for (int i = 0; i < 4; i++)
            g_rowmax[r0 + ty * 4 + i] = rmax[i];
    }
}

// ---------------- per-row softmax normalize in place ----------------
__global__ __launch_bounds__(128) void softmax_kernel(
    float* __restrict__ attn, const int* __restrict__ x_batch)
{
    const int i = blockIdx.x;
    const int g = x_batch[i];
    const int fs = g_foff[g], fe = g_foff[g + 1];
    const float m = g_rowmax[i];
    float* row = attn + (size_t)i * NF;
    const int t = threadIdx.x;

    float s = 0.f;
    for (int j = fs + t; j < fe; j += 128) s += expf(row[j] - m);

    __shared__ float red[4];
#pragma unroll
    for (int o = 16; o; o >>= 1) s += __shfl_xor_sync(0xffffffffu, s, o);
    if ((t & 31) == 0) red[t >> 5] = s;
    __syncthreads();
    float tot = red[0] + red[1] + red[2] + red[3];
    float inv = 1.f / tot;

    for (int j = fs + t; j < fe; j += 128) row[j] = expf(row[j] - m) * inv;
}

// ---------------- context = attn(block) @ value(block) ----------------
// grid: (OUT_SIZE/64, NX/64), 256 threads
__global__ __launch_bounds__(256) void context_kernel(
    const float* __restrict__ attn, float* __restrict__ ctx,
    const int* __restrict__ x_batch)
{
    __shared__ float As[16][64];   // As[k][r] = attn[r][k]
    __shared__ float Bs[16][64];   // Bs[k][n] = value[k][n]
    __shared__ int sjmin, sjmax;

    const int t = threadIdx.x;
    const int r0 = blockIdx.y * 64;
    const int n0 = blockIdx.x * 64;
    const int tx = t & 15, ty = t >> 4;

    if (t == 0) {
        int g0 = x_batch[r0], g1 = x_batch[r0 + 63];
        sjmin = g_foff[g0];
        sjmax = g_foff[g1 + 1];
    }
    __syncthreads();

    const int kmin = sjmin & ~15, kmax = sjmax;
    const int arow = t >> 2, acol4 = (t & 3) * 4;
    const int brow = t >> 4, bcol4 = (t & 15) * 4;

    float acc[4][4] = {};

    for (int k0 = kmin; k0 < kmax; k0 += 16) {
        // attn outside [fs,fe) per row is exactly 0 (memset), so no masking needed
        float4 av = *(const float4*)(attn + (size_t)(r0 + arow) * NF + k0 + acol4);
        As[acol4 + 0][arow] = av.x;
        As[acol4 + 1][arow] = av.y;
        As[acol4 + 2][arow] = av.z;
        As[acol4 + 3][arow] = av.w;
        *(float4*)&Bs[brow][bcol4] =
            *(const float4*)(g_value + (size_t)(k0 + brow) * OUT_SIZE + n0 + bcol4);
        __syncthreads();
#pragma unroll
        for (int k = 0; k < 16; k++) {
            float4 a = *(const float4*)&As[k][ty * 4];
            float4 b = *(const float4*)&Bs[k][tx * 4];
            FMA16(acc, a, b);
        }
        __syncthreads();
    }
#pragma unroll
    for (int i = 0; i < 4; i++) {
        float4 v = make_float4(acc[i][0], acc[i][1], acc[i][2], acc[i][3]);
        *(float4*)(ctx + (size_t)(r0 + ty * 4 + i) * OUT_SIZE + n0 + tx * 4) = v;
    }
}

// ---------------- launch ----------------
extern "C" void kernel_launch(void* const* d_in, const int* in_sizes, int n_in,
                              void* d_out, int out_size)
{
    const float* f       = (const float*)d_in[0];
    const float* h       = (const float*)d_in[2];
    const int*   f_batch = (const int*)  d_in[5];
    const int*   x_batch = (const int*)  d_in[6];
    const float* W_h     = (const float*)d_in[8];
    const float* W_key   = (const float*)d_in[9];
    const float* W_value = (const float*)d_in[10];

    float* out  = (float*)d_out;
    float* ctx  = out;                            // [NX, OUT_SIZE]
    float* attn = out + (size_t)NX * OUT_SIZE;    // [NX, NF]

    offsets_kernel<<<1, 32>>>(f_batch);

    // query = h @ W_h        [8192,256]x[256,128]
    sgemm64<<<dim3(D_ATT / 64, NX / 64), 256>>>(h, W_h, 0, D_ATT, OUT_SIZE);
    // key = f @ W_key        [8192,512]x[512,128]
    sgemm64<<<dim3(D_ATT / 64, NF / 64), 256>>>(f, W_key, 1, D_ATT, F_SIZE);
    // value = f @ W_value    [8192,512]x[512,256]
    sgemm64<<<dim3(OUT_SIZE / 64, NF / 64), 256>>>(f, W_value, 2, OUT_SIZE, F_SIZE);

    // zero the full attn output (masked entries are exactly 0 in fp32 softmax)
    cudaMemsetAsync(attn, 0, (size_t)NX * NF * sizeof(float), 0);

    scores_kernel<<<NX / 64, 256>>>(x_batch, attn);
    softmax_kernel<<<NX, 128>>>(attn, x_batch);
    context_kernel<<<dim3(OUT_SIZE / 64, NX / 64), 256>>>(attn, ctx, x_batch);
}

// round 3
// speedup vs baseline: 1.7405x; 1.7384x over previous
#include <cuda_runtime.h>
#include <cuda_bf16.h>
#include <cstdint>

#define NX 8192
#define NF 8192
#define F_SIZE 512
#define OUT_SIZE 256
#define D_ATT 128
#define N_GRAPHS 16

__device__ float g_query[NX * D_ATT];
__device__ float g_key[NF * D_ATT];
__device__ float g_value[NF * OUT_SIZE];
__device__ int   g_foff[N_GRAPHS + 1];

__global__ void offsets_kernel(const int* __restrict__ f_batch) {
    int g = threadIdx.x;
    if (g > N_GRAPHS) return;
    int lo = 0, hi = NF;
    while (lo < hi) { int mid = (lo + hi) >> 1; if (f_batch[mid] < g) lo = mid + 1; else hi = mid; }
    g_foff[g] = lo;
}

// ---------- PTX helpers ----------
__device__ __forceinline__ unsigned su(const void* p) { return (unsigned)__cvta_generic_to_shared(p); }
__device__ __forceinline__ void ldsm4(unsigned r[4], unsigned a) {
    asm volatile("ldmatrix.sync.aligned.m8n8.x4.shared.b16 {%0,%1,%2,%3},[%4];"
        : "=r"(r[0]), "=r"(r[1]), "=r"(r[2]), "=r"(r[3]) : "r"(a));
}
__device__ __forceinline__ void ldsm4t(unsigned r[4], unsigned a) {
    asm volatile("ldmatrix.sync.aligned.m8n8.x4.trans.shared.b16 {%0,%1,%2,%3},[%4];"
        : "=r"(r[0]), "=r"(r[1]), "=r"(r[2]), "=r"(r[3]) : "r"(a));
}
__device__ __forceinline__ void mma_bf(float d[4], const unsigned a[4], unsigned b0, unsigned b1) {
    asm volatile("mma.sync.aligned.m16n8k16.row.col.f32.bf16.bf16.f32 "
        "{%0,%1,%2,%3},{%4,%5,%6,%7},{%8,%9},{%0,%1,%2,%3};"
        : "+f"(d[0]), "+f"(d[1]), "+f"(d[2]), "+f"(d[3])
        : "r"(a[0]), "r"(a[1]), "r"(a[2]), "r"(a[3]), "r"(b0), "r"(b1));
}
__device__ __forceinline__ unsigned pk2(__nv_bfloat16 a, __nv_bfloat16 b) {
    __nv_bfloat162 t(a, b); return *reinterpret_cast<unsigned*>(&t);
}
__device__ __forceinline__ void split4(float4 v, uint2& hi, uint2& lo) {
    __nv_bfloat16 h0 = __float2bfloat16_rn(v.x), h1 = __float2bfloat16_rn(v.y);
    __nv_bfloat16 h2 = __float2bfloat16_rn(v.z), h3 = __float2bfloat16_rn(v.w);
    __nv_bfloat16 l0 = __float2bfloat16_rn(v.x - __bfloat162float(h0));
    __nv_bfloat16 l1 = __float2bfloat16_rn(v.y - __bfloat162float(h1));
    __nv_bfloat16 l2 = __float2bfloat16_rn(v.z - __bfloat162float(h2));
    __nv_bfloat16 l3 = __float2bfloat16_rn(v.w - __bfloat162float(h3));
    hi.x = pk2(h0, h1); hi.y = pk2(h2, h3);
    lo.x = pk2(l0, l1); lo.y = pk2(l2, l3);
}

// =====================================================================
// bf16x3 tensor GEMM: C[M,N] = A[M,K] @ B[K,N]. BM=128 BN=64 BK=32.
// 256 thr, 8 warps (4m x 2n), warp tile 32x32. DYNK: k-band from offsets.
// =====================================================================
template<bool DYNK>
__global__ __launch_bounds__(256) void gemm_tc(
    const float* __restrict__ A, int lda, const float* __restrict__ B, int ldb,
    float* __restrict__ C, int ldc, int K, const int* __restrict__ xb)
{
    __shared__ __align__(16) __nv_bfloat16 Ah[128 * 40], Al[128 * 40], Bh[32 * 72], Bl[32 * 72];
    const int tid = threadIdx.x, lane = tid & 31, wid = tid >> 5, wm = wid >> 1, wn = wid & 1;
    const int m0 = blockIdx.y * 128, n0 = blockIdx.x * 64;

    int kbeg = 0, kend = K, klim = K;
    if (DYNK) {
        int g0 = xb[m0], g1 = xb[m0 + 127];
        kbeg = g_foff[g0] & ~31; kend = g_foff[g1 + 1]; klim = NF;
    }
    float acc[2][4][4] = {};

    for (int k0 = kbeg; k0 < kend; k0 += 32) {
#pragma unroll
        for (int i = 0; i < 4; i++) {
            int idx = tid + i * 256, r = idx >> 3, c4 = (idx & 7) << 2, kk = k0 + c4;
            float4 v = (kk < klim) ? *(const float4*)(A + (size_t)(m0 + r) * lda + kk)
                                   : make_float4(0.f, 0.f, 0.f, 0.f);
            uint2 h_, l_; split4(v, h_, l_);
            *(uint2*)(Ah + r * 40 + c4) = h_;
            *(uint2*)(Al + r * 40 + c4) = l_;
        }
#pragma unroll
        for (int i = 0; i < 2; i++) {
            int idx = tid + i * 256, r = idx >> 4, c4 = (idx & 15) << 2, kk = k0 + r;
            float4 v = (kk < klim) ? *(const float4*)(B + (size_t)kk * ldb + n0 + c4)
                                   : make_float4(0.f, 0.f, 0.f, 0.f);
            uint2 h_, l_; split4(v, h_, l_);
            *(uint2*)(Bh + r * 72 + c4) = h_;
            *(uint2*)(Bl + r * 72 + c4) = l_;
        }
        __syncthreads();
#pragma unroll
        for (int ks = 0; ks < 32; ks += 16) {
            unsigned ah[2][4], al[2][4], bh[2][4], bl[2][4];
#pragma unroll
            for (int mf = 0; mf < 2; mf++) {
                unsigned off = 2u * ((wm * 32 + mf * 16 + (lane & 15)) * 40 + ks + ((lane >> 4) << 3));
                ldsm4(ah[mf], su(Ah) + off);
                ldsm4(al[mf], su(Al) + off);
            }
#pragma unroll
            for (int p = 0; p < 2; p++) {
                unsigned off = 2u * ((ks + (lane & 15)) * 72 + wn * 32 + p * 16 + ((lane >> 4) << 3));
                ldsm4t(bh[p], su(Bh) + off);
                ldsm4t(bl[p], su(Bl) + off);
            }
#pragma unroll
            for (int mf = 0; mf < 2; mf++)
#pragma unroll
                for (int nf = 0; nf < 4; nf++) {
                    unsigned b0 = bh[nf >> 1][(nf & 1) * 2], b1 = bh[nf >> 1][(nf & 1) * 2 + 1];
                    unsigned c0 = bl[nf >> 1][(nf & 1) * 2], c1 = bl[nf >> 1][(nf & 1) * 2 + 1];
                    mma_bf(acc[mf][nf], ah[mf], b0, b1);
                    mma_bf(acc[mf][nf], al[mf], b0, b1);
                    mma_bf(acc[mf][nf], ah[mf], c0, c1);
                }
        }
        __syncthreads();
    }
#pragma unroll
    for (int mf = 0; mf < 2; mf++)
#pragma unroll
        for (int nf = 0; nf < 4; nf++) {
            int row = m0 + wm * 32 + mf * 16 + (lane >> 2);
            int col = n0 + wn * 32 + nf * 8 + ((lane & 3) << 1);
            *(float2*)(C + (size_t)row * ldc + col) = make_float2(acc[mf][nf][0], acc[mf][nf][1]);
            *(float2*)(C + (size_t)(row + 8) * ldc + col) = make_float2(acc[mf][nf][2], acc[mf][nf][3]);
        }
}

// =====================================================================
// scores: band tiles only. S[128 x 64] = Q[128x128] @ K[64x128]^T.
// grid (8 colparts, NX/128). Q resident in smem; masked epilogue.
// =====================================================================
#define QLD 136
__global__ __launch_bounds__(256) void scores_tc(
    const int* __restrict__ xb, float* __restrict__ attn)
{
    extern __shared__ __align__(16) __nv_bfloat16 sm[];
    __nv_bfloat16* Qh = sm;
    __nv_bfloat16* Ql = Qh + 128 * QLD;
    __nv_bfloat16* Kh = Ql + 128 * QLD;
    __nv_bfloat16* Kl = Kh + 64 * QLD;

    const int tid = threadIdx.x, lane = tid & 31, wid = tid >> 5, wm = wid >> 1, wn = wid & 1;
    const int m0 = blockIdx.y * 128;

    const int jmin = g_foff[xb[m0]];
    const int jmax = g_foff[xb[m0 + 127] + 1];
    const int jt_lo = jmin >> 6, jt_hi = (jmax + 63) >> 6;
    if (jt_lo + (int)blockIdx.x >= jt_hi) return;

    int fs[2][2], fe[2][2];
#pragma unroll
    for (int mf = 0; mf < 2; mf++)
#pragma unroll
        for (int hh = 0; hh < 2; hh++) {
            int row = m0 + wm * 32 + mf * 16 + (lane >> 2) + hh * 8;
            int g = xb[row];
            fs[mf][hh] = g_foff[g]; fe[mf][hh] = g_foff[g + 1];
        }

#pragma unroll
    for (int i = 0; i < 16; i++) {
        int idx = tid + i * 256, r = idx >> 5, c4 = (idx & 31) << 2;
        float4 v = *(const float4*)(g_query + (size_t)(m0 + r) * D_ATT + c4);
        uint2 h_, l_; split4(v, h_, l_);
        *(uint2*)(Qh + r * QLD + c4) = h_;
        *(uint2*)(Ql + r * QLD + c4) = l_;
    }

    for (int jt = jt_lo + blockIdx.x; jt < jt_hi; jt += 8) {
        const int j0 = jt << 6;
#pragma unroll
        for (int i = 0; i < 8; i++) {
            int idx = tid + i * 256, r = idx >> 5, c4 = (idx & 31) << 2;
            float4 v = *(const float4*)(g_key + (size_t)(j0 + r) * D_ATT + c4);
            uint2 h_, l_; split4(v, h_, l_);
            *(uint2*)(Kh + r * QLD + c4) = h_;
            *(uint2*)(Kl + r * QLD + c4) = l_;
        }
        __syncthreads();

        float acc[2][4][4] = {};
#pragma unroll
        for (int d0 = 0; d0 < D_ATT; d0 += 16) {
            unsigned ah[2][4], al[2][4], bh[2][4], bl[2][4];
#pragma unroll
            for (int mf = 0; mf < 2; mf++) {
                unsigned off = 2u * ((wm * 32 + mf * 16 + (lane & 15)) * QLD + d0 + ((lane >> 4) << 3));
                ldsm4(ah[mf], su(Qh) + off);
                ldsm4(al[mf], su(Ql) + off);
            }
#pragma unroll
            for (int p = 0; p < 2; p++) {
                unsigned off = 2u * ((wn * 32 + p * 16 + ((lane >> 4) << 3) + (lane & 7)) * QLD + d0 + (lane & 8));
                ldsm4(bh[p], su(Kh) + off);
                ldsm4(bl[p], su(Kl) + off);
            }
#pragma unroll
            for (int mf = 0; mf < 2; mf++)
#pragma unroll
                for (int nf = 0; nf < 4; nf++) {
                    unsigned b0 = bh[nf >> 1][(nf & 1) * 2], b1 = bh[nf >> 1][(nf & 1) * 2 + 1];
                    unsigned c0 = bl[nf >> 1][(nf & 1) * 2], c1 = bl[nf >> 1][(nf & 1) * 2 + 1];
                    mma_bf(acc[mf][nf], ah[mf], b0, b1);
                    mma_bf(acc[mf][nf], al[mf], b0, b1);
                    mma_bf(acc[mf][nf], ah[mf], c0, c1);
                }
        }
        __syncthreads();

#pragma unroll
        for (int mf = 0; mf < 2; mf++) {
            int row = m0 + wm * 32 + mf * 16 + (lane >> 2);
#pragma unroll
            for (int nf = 0; nf < 4; nf++) {
                int col = j0 + wn * 32 + nf * 8 + ((lane & 3) << 1);
                float2 w0, w1;
                w0.x = (col >= fs[mf][0] && col < fe[mf][0])     ? acc[mf][nf][0] : 0.f;
                w0.y = (col + 1 >= fs[mf][0] && col + 1 < fe[mf][0]) ? acc[mf][nf][1] : 0.f;
                w1.x = (col >= fs[mf][1] && col < fe[mf][1])     ? acc[mf][nf][2] : 0.f;
                w1.y = (col + 1 >= fs[mf][1] && col + 1 < fe[mf][1]) ? acc[mf][nf][3] : 0.f;
                *(float2*)(attn + (size_t)row * NF + col) = w0;
                *(float2*)(attn + (size_t)(row + 8) * NF + col) = w1;
            }
        }
    }
}

__global__ void zero_attn(float4* __restrict__ p, size_t n) {
    size_t i = (size_t)blockIdx.x * blockDim.x + threadIdx.x;
    size_t s = (size_t)gridDim.x * blockDim.x;
    float4 z = make_float4(0.f, 0.f, 0.f, 0.f);
    for (; i < n; i += s) p[i] = z;
}

__global__ __launch_bounds__(128) void softmax_kernel(
    float* __restrict__ attn, const int* __restrict__ xb)
{
    const int i = blockIdx.x, t = threadIdx.x;
    const int g = xb[i], fs = g_foff[g], fe = g_foff[g + 1];
    float* row = attn + (size_t)i * NF;
    __shared__ float red[4];

    float m = -3.0e38f;
    for (int j = fs + t; j < fe; j += 128) m = fmaxf(m, row[j]);
#pragma unroll
    for (int o = 16; o; o >>= 1) m = fmaxf(m, __shfl_xor_sync(0xffffffffu, m, o));
    if ((t & 31) == 0) red[t >> 5] = m;
    __syncthreads();
    m = fmaxf(fmaxf(red[0], red[1]), fmaxf(red[2], red[3]));
    __syncthreads();

    float s = 0.f;
    for (int j = fs + t; j < fe; j += 128) s += expf(row[j] - m);
#pragma unroll
    for (int o = 16; o; o >>= 1) s += __shfl_xor_sync(0xffffffffu, s, o);
    if ((t & 31) == 0) red[t >> 5] = s;
    __syncthreads();
    float inv = 1.f / (red[0] + red[1] + red[2] + red[3]);

    for (int j = fs + t; j < fe; j += 128) row[j] = expf(row[j] - m) * inv;
}

// ---------------- launch ----------------
extern "C" void kernel_launch(void* const* d_in, const int* in_sizes, int n_in,
                              void* d_out, int out_size)
{
    const float* f       = (const float*)d_in[0];
    const float* h       = (const float*)d_in[2];
    const int*   f_batch = (const int*)  d_in[5];
    const int*   x_batch = (const int*)  d_in[6];
    const float* W_h     = (const float*)d_in[8];
    const float* W_key   = (const float*)d_in[9];
    const float* W_value = (const float*)d_in[10];

    float* out  = (float*)d_out;
    float* ctx  = out;
    float* attn = out + (size_t)NX * OUT_SIZE;

    float *pq, *pk, *pv;
    cudaGetSymbolAddress((void**)&pq, g_query);
    cudaGetSymbolAddress((void**)&pk, g_key);
    cudaGetSymbolAddress((void**)&pv, g_value);

    const int sc_smem = (2 * 128 * QLD + 2 * 64 * QLD) * 2;  // 104448 B
    cudaFuncSetAttribute(scores_tc, cudaFuncAttributeMaxDynamicSharedMemorySize, sc_smem);

    offsets_kernel<<<1, 32>>>(f_batch);
    zero_attn<<<4096, 256>>>((float4*)attn, (size_t)NX * NF / 4);

    gemm_tc<false><<<dim3(D_ATT / 64, NX / 128), 256>>>(h, OUT_SIZE, W_h, D_ATT, pq, D_ATT, OUT_SIZE, nullptr);
    gemm_tc<false><<<dim3(D_ATT / 64, NF / 128), 256>>>(f, F_SIZE, W_key, D_ATT, pk, D_ATT, F_SIZE, nullptr);
    gemm_tc<false><<<dim3(OUT_SIZE / 64, NF / 128), 256>>>(f, F_SIZE, W_value, OUT_SIZE, pv, OUT_SIZE, F_SIZE, nullptr);

    scores_tc<<<dim3(8, NX / 128), 256, sc_smem>>>(x_batch, attn);
    softmax_kernel<<<NX, 128>>>(attn, x_batch);

    gemm_tc<true><<<dim3(OUT_SIZE / 64, NX / 128), 256>>>(attn, NF, pv, OUT_SIZE, ctx, OUT_SIZE, NF, x_batch);
}

// round 4
// speedup vs baseline: 2.2867x; 1.3138x over previous
#include <cuda_runtime.h>
#include <cuda_bf16.h>
#include <cstdint>

#define NX 8192
#define NF 8192
#define F_SIZE 512
#define OUT_SIZE 256
#define D_ATT 128
#define N_GRAPHS 16

// ---------------- scratch ----------------
__device__ int g_foff[N_GRAPHS + 1];
__device__ __nv_bfloat16 g_fh[NF * F_SIZE],  g_fl[NF * F_SIZE];    // 8+8 MB
__device__ __nv_bfloat16 g_hh[NX * OUT_SIZE], g_hl[NX * OUT_SIZE]; // 4+4 MB
__device__ __nv_bfloat16 g_qh[NX * D_ATT],   g_ql[NX * D_ATT];
__device__ __nv_bfloat16 g_kh[NF * D_ATT],   g_kl[NF * D_ATT];
__device__ __nv_bfloat16 g_vh[NF * OUT_SIZE], g_vl[NF * OUT_SIZE];
#define W_TOT (256 * 128 + 512 * 128 + 512 * 256)
__device__ __nv_bfloat16 g_wh[W_TOT], g_wl[W_TOT];
#define WOFF_Q 0
#define WOFF_K 32768
#define WOFF_V 98304

__global__ void offsets_kernel(const int* __restrict__ f_batch) {
    int g = threadIdx.x;
    if (g > N_GRAPHS) return;
    int lo = 0, hi = NF;
    while (lo < hi) { int mid = (lo + hi) >> 1; if (f_batch[mid] < g) lo = mid + 1; else hi = mid; }
    g_foff[g] = lo;
}

// ---------------- helpers ----------------
__device__ __forceinline__ unsigned su(const void* p) { return (unsigned)__cvta_generic_to_shared(p); }
__device__ __forceinline__ void cpa16(void* dst, const void* src) {
    asm volatile("cp.async.cg.shared.global [%0],[%1],16;\n" :: "r"(su(dst)), "l"(src));
}
#define CPA_COMMIT asm volatile("cp.async.commit_group;\n")
#define CPA_WAIT1  asm volatile("cp.async.wait_group 1;\n")
#define CPA_WAIT0  asm volatile("cp.async.wait_group 0;\n")

__device__ __forceinline__ void ldsm4(unsigned r[4], unsigned a) {
    asm volatile("ldmatrix.sync.aligned.m8n8.x4.shared.b16 {%0,%1,%2,%3},[%4];"
        : "=r"(r[0]), "=r"(r[1]), "=r"(r[2]), "=r"(r[3]) : "r"(a));
}
__device__ __forceinline__ void ldsm4t(unsigned r[4], unsigned a) {
    asm volatile("ldmatrix.sync.aligned.m8n8.x4.trans.shared.b16 {%0,%1,%2,%3},[%4];"
        : "=r"(r[0]), "=r"(r[1]), "=r"(r[2]), "=r"(r[3]) : "r"(a));
}
__device__ __forceinline__ void mma_bf(float d[4], const unsigned a[4], unsigned b0, unsigned b1) {
    asm volatile("mma.sync.aligned.m16n8k16.row.col.f32.bf16.bf16.f32 "
        "{%0,%1,%2,%3},{%4,%5,%6,%7},{%8,%9},{%0,%1,%2,%3};"
        : "+f"(d[0]), "+f"(d[1]), "+f"(d[2]), "+f"(d[3])
        : "r"(a[0]), "r"(a[1]), "r"(a[2]), "r"(a[3]), "r"(b0), "r"(b1));
}
__device__ __forceinline__ unsigned pk2(__nv_bfloat16 a, __nv_bfloat16 b) {
    __nv_bfloat162 t(a, b); return *reinterpret_cast<unsigned*>(&t);
}
__device__ __forceinline__ void split4(float4 v, uint2& hi, uint2& lo) {
    __nv_bfloat16 h0 = __float2bfloat16_rn(v.x), h1 = __float2bfloat16_rn(v.y);
    __nv_bfloat16 h2 = __float2bfloat16_rn(v.z), h3 = __float2bfloat16_rn(v.w);
    __nv_bfloat16 l0 = __float2bfloat16_rn(v.x - __bfloat162float(h0));
    __nv_bfloat16 l1 = __float2bfloat16_rn(v.y - __bfloat162float(h1));
    __nv_bfloat16 l2 = __float2bfloat16_rn(v.z - __bfloat162float(h2));
    __nv_bfloat16 l3 = __float2bfloat16_rn(v.w - __bfloat162float(h3));
    hi.x = pk2(h0, h1); hi.y = pk2(h2, h3);
    lo.x = pk2(l0, l1); lo.y = pk2(l2, l3);
}
__device__ __forceinline__ void split2w(float x, float y, unsigned& h, unsigned& l) {
    __nv_bfloat16 hx = __float2bfloat16_rn(x), hy = __float2bfloat16_rn(y);
    h = pk2(hx, hy);
    l = pk2(__float2bfloat16_rn(x - __bfloat162float(hx)),
            __float2bfloat16_rn(y - __bfloat162float(hy)));
}

// ---------------- fp32 -> bf16 hi/lo conversion ----------------
__global__ void split_arr(const float4* __restrict__ src,
                          __nv_bfloat16* __restrict__ dh,
                          __nv_bfloat16* __restrict__ dl, int n4) {
    int i = blockIdx.x * blockDim.x + threadIdx.x;
    int s = gridDim.x * blockDim.x;
    for (; i < n4; i += s) {
        uint2 h, l; split4(src[i], h, l);
        ((uint2*)dh)[i] = h;
        ((uint2*)dl)[i] = l;
    }
}

__global__ void zero_attn(float4* __restrict__ p, size_t n) {
    size_t i = (size_t)blockIdx.x * blockDim.x + threadIdx.x;
    size_t s = (size_t)gridDim.x * blockDim.x;
    float4 z = make_float4(0.f, 0.f, 0.f, 0.f);
    for (; i < n; i += s) p[i] = z;
}

// =====================================================================
// Fused projections: all bf16 hi/lo pre-split inputs, cp.async double buffer.
// BM=128 BN=64 BK=32, 8 warps (4m x 2n). 512 blocks: q(128) k(128) v(256).
// =====================================================================
#define AE 5120   // 128*40 bf16 elems
#define BE 2304   // 32*72
#define STG (2 * AE + 2 * BE)   // 14848 elems
#define PROJ_SMEM (2 * STG * 2) // 59392 bytes

__global__ __launch_bounds__(256) void proj_tc() {
    extern __shared__ __align__(16) __nv_bfloat16 dsm[];
    const int tid = threadIdx.x, lane = tid & 31, wid = tid >> 5, wm = wid >> 1, wn = wid & 1;
    const int b = blockIdx.x;

    const __nv_bfloat16 *Agh, *Agl, *Bgh, *Bgl;
    __nv_bfloat16 *Coh, *Col;
    int lda, ldb, ldc, K, m0, n0;
    if (b < 128) {
        Agh = g_hh; Agl = g_hl; lda = OUT_SIZE; K = OUT_SIZE;
        Bgh = g_wh + WOFF_Q; Bgl = g_wl + WOFF_Q; ldb = D_ATT; ldc = D_ATT;
        Coh = g_qh; Col = g_ql; m0 = (b >> 1) * 128; n0 = (b & 1) * 64;
    } else if (b < 256) {
        int lb = b - 128;
        Agh = g_fh; Agl = g_fl; lda = F_SIZE; K = F_SIZE;
        Bgh = g_wh + WOFF_K; Bgl = g_wl + WOFF_K; ldb = D_ATT; ldc = D_ATT;
        Coh = g_kh; Col = g_kl; m0 = (lb >> 1) * 128; n0 = (lb & 1) * 64;
    } else {
        int lb = b - 256;
        Agh = g_fh; Agl = g_fl; lda = F_SIZE; K = F_SIZE;
        Bgh = g_wh + WOFF_V; Bgl = g_wl + WOFF_V; ldb = OUT_SIZE; ldc = OUT_SIZE;
        Coh = g_vh; Col = g_vl; m0 = (lb >> 2) * 128; n0 = (lb & 3) * 64;
    }

    auto pf = [&](int k0, int s) {
        __nv_bfloat16* bs = dsm + s * STG;
#pragma unroll
        for (int i = 0; i < 2; i++) {
            int idx = tid + i * 256, r = idx >> 2, c8 = (idx & 3) * 8;
            cpa16(bs + r * 40 + c8, Agh + (size_t)(m0 + r) * lda + k0 + c8);
            cpa16(bs + AE + r * 40 + c8, Agl + (size_t)(m0 + r) * lda + k0 + c8);
        }
        {
            int r = tid >> 3, c8 = (tid & 7) * 8;
            cpa16(bs + 2 * AE + r * 72 + c8, Bgh + (size_t)(k0 + r) * ldb + n0 + c8);
            cpa16(bs + 2 * AE + BE + r * 72 + c8, Bgl + (size_t)(k0 + r) * ldb + n0 + c8);
        }
        CPA_COMMIT;
    };

    float acc[2][4][4] = {};
    const unsigned smB = su(dsm);

    auto compute = [&](int s) {
        unsigned aB = smB + 2 * (s * STG);
        unsigned alB = aB + 2 * AE;
        unsigned bB = aB + 2 * (2 * AE);
        unsigned blB = bB + 2 * BE;
#pragma unroll
        for (int ks = 0; ks < 32; ks += 16) {
            unsigned ah[2][4], al[2][4], bh[2][4], bl[2][4];
#pragma unroll
            for (int mf = 0; mf < 2; mf++) {
                unsigned off = 2u * ((wm * 32 + mf * 16 + (lane & 15)) * 40 + ks + ((lane >> 4) << 3));
                ldsm4(ah[mf], aB + off);
                ldsm4(al[mf], alB + off);
            }
#pragma unroll
            for (int p = 0; p < 2; p++) {
                unsigned off = 2u * ((ks + (lane & 15)) * 72 + wn * 32 + p * 16 + ((lane >> 4) << 3));
                ldsm4t(bh[p], bB + off);
                ldsm4t(bl[p], blB + off);
            }
#pragma unroll
            for (int mf = 0; mf < 2; mf++)
#pragma unroll
                for (int nf = 0; nf < 4; nf++) {
                    unsigned b0 = bh[nf >> 1][(nf & 1) * 2], b1 = bh[nf >> 1][(nf & 1) * 2 + 1];
                    unsigned c0 = bl[nf >> 1][(nf & 1) * 2], c1 = bl[nf >> 1][(nf & 1) * 2 + 1];
                    mma_bf(acc[mf][nf], ah[mf], b0, b1);
                    mma_bf(acc[mf][nf], al[mf], b0, b1);
                    mma_bf(acc[mf][nf], ah[mf], c0, c1);
                }
        }
    };

    const int nst = K / 32;
    pf(0, 0);
    for (int t = 0; t < nst; t++) {
        int s = t & 1;
        if (t + 1 < nst) { pf((t + 1) * 32, s ^ 1); CPA_WAIT1; } else { CPA_WAIT0; }
        __syncthreads();
        compute(s);
        __syncthreads();
    }

#pragma unroll
    for (int mf = 0; mf < 2; mf++)
#pragma unroll
        for (int nf = 0; nf < 4; nf++) {
            int row = m0 + wm * 32 + mf * 16 + (lane >> 2);
            int col = n0 + wn * 32 + nf * 8 + ((lane & 3) << 1);
            unsigned h0, l0, h1, l1;
            split2w(acc[mf][nf][0], acc[mf][nf][1], h0, l0);
            split2w(acc[mf][nf][2], acc[mf][nf][3], h1, l1);
            *(unsigned*)(Coh + (size_t)row * ldc + col) = h0;
            *(unsigned*)(Col + (size_t)row * ldc + col) = l0;
            *(unsigned*)(Coh + (size_t)(row + 8) * ldc + col) = h1;
            *(unsigned*)(Col + (size_t)(row + 8) * ldc + col) = l1;
        }
}

// =====================================================================
// scores: S[128x64] = Q @ K^T on band tiles, bf16 pre-split inputs.
// grid (8 colparts, NX/128). Q smem-resident via cp.async.
// =====================================================================
#define QLD 136
#define QE (128 * QLD)
#define KE (64 * QLD)
#define SC_SMEM ((2 * QE + 2 * KE) * 2)   // 104448 bytes

__global__ __launch_bounds__(256) void scores_tc(
    const int* __restrict__ xb, float* __restrict__ attn)
{
    extern __shared__ __align__(16) __nv_bfloat16 dsm[];
    __nv_bfloat16* Qh = dsm;
    __nv_bfloat16* Ql = Qh + QE;
    __nv_bfloat16* Kh = Ql + QE;
    __nv_bfloat16* Kl = Kh + KE;

    const int tid = threadIdx.x, lane = tid & 31, wid = tid >> 5, wm = wid >> 1, wn = wid & 1;
    const int m0 = blockIdx.y * 128;

    const int jmin = g_foff[xb[m0]];
    const int jmax = g_foff[xb[m0 + 127] + 1];
    const int jt_lo = jmin >> 6, jt_hi = (jmax + 63) >> 6;
    if (jt_lo + (int)blockIdx.x >= jt_hi) return;

    int fs[2][2], fe[2][2];
#pragma unroll
    for (int mf = 0; mf < 2; mf++)
#pragma unroll
        for (int hh = 0; hh < 2; hh++) {
            int row = m0 + wm * 32 + mf * 16 + (lane >> 2) + hh * 8;
            int g = xb[row];
            fs[mf][hh] = g_foff[g]; fe[mf][hh] = g_foff[g + 1];
        }

#pragma unroll
    for (int i = 0; i < 8; i++) {
        int idx = tid + i * 256, r = idx >> 4, c8 = (idx & 15) * 8;
        cpa16(Qh + r * QLD + c8, g_qh + (size_t)(m0 + r) * D_ATT + c8);
        cpa16(Ql + r * QLD + c8, g_ql + (size_t)(m0 + r) * D_ATT + c8);
    }
    CPA_COMMIT;

    const unsigned qhB = su(Qh), qlB = su(Ql), khB = su(Kh), klB = su(Kl);

    for (int jt = jt_lo + blockIdx.x; jt < jt_hi; jt += 8) {
        const int j0 = jt << 6;
#pragma unroll
        for (int i = 0; i < 4; i++) {
            int idx = tid + i * 256, r = idx >> 4, c8 = (idx & 15) * 8;
            cpa16(Kh + r * QLD + c8, g_kh + (size_t)(j0 + r) * D_ATT + c8);
            cpa16(Kl + r * QLD + c8, g_kl + (size_t)(j0 + r) * D_ATT + c8);
        }
        CPA_COMMIT;
        CPA_WAIT0;
        __syncthreads();

        float acc[2][4][4] = {};
#pragma unroll
        for (int d0 = 0; d0 < D_ATT; d0 += 16) {
            unsigned ah[2][4], al[2][4], bh[2][4], bl[2][4];
#pragma unroll
            for (int mf = 0; mf < 2; mf++) {
                unsigned off = 2u * ((wm * 32 + mf * 16 + (lane & 15)) * QLD + d0 + ((lane >> 4) << 3));
                ldsm4(ah[mf], qhB + off);
                ldsm4(al[mf], qlB + off);
            }
#pragma unroll
            for (int p = 0; p < 2; p++) {
                unsigned off = 2u * ((wn * 32 + p * 16 + ((lane >> 4) << 3) + (lane & 7)) * QLD + d0 + (lane & 8));
                ldsm4(bh[p], khB + off);
                ldsm4(bl[p], klB + off);
            }
#pragma unroll
            for (int mf = 0; mf < 2; mf++)
#pragma unroll
                for (int nf = 0; nf < 4; nf++) {
                    unsigned b0 = bh[nf >> 1][(nf & 1) * 2], b1 = bh[nf >> 1][(nf & 1) * 2 + 1];
                    unsigned c0 = bl[nf >> 1][(nf & 1) * 2], c1 = bl[nf >> 1][(nf & 1) * 2 + 1];
                    mma_bf(acc[mf][nf], ah[mf], b0, b1);
                    mma_bf(acc[mf][nf], al[mf], b0, b1);
                    mma_bf(acc[mf][nf], ah[mf], c0, c1);
                }
        }
        __syncthreads();

#pragma unroll
        for (int mf = 0; mf < 2; mf++) {
            int row = m0 + wm * 32 + mf * 16 + (lane >> 2);
#pragma unroll
            for (int nf = 0; nf < 4; nf++) {
                int col = j0 + wn * 32 + nf * 8 + ((lane & 3) << 1);
                float2 w0, w1;
                w0.x = (col >= fs[mf][0] && col < fe[mf][0])         ? acc[mf][nf][0] : 0.f;
                w0.y = (col + 1 >= fs[mf][0] && col + 1 < fe[mf][0]) ? acc[mf][nf][1] : 0.f;
                w1.x = (col >= fs[mf][1] && col < fe[mf][1])         ? acc[mf][nf][2] : 0.f;
                w1.y = (col + 1 >= fs[mf][1] && col + 1 < fe[mf][1]) ? acc[mf][nf][3] : 0.f;
                *(float2*)(attn + (size_t)row * NF + col) = w0;
                *(float2*)(attn + (size_t)(row + 8) * NF + col) = w1;
            }
        }
    }
}

// =====================================================================
// softmax (in place over band)
// =====================================================================
__global__ __launch_bounds__(128) void softmax_kernel(
    float* __restrict__ attn, const int* __restrict__ xb)
{
    const int i = blockIdx.x, t = threadIdx.x;
    const int g = xb[i], fs = g_foff[g], fe = g_foff[g + 1];
    float* row = attn + (size_t)i * NF;
    __shared__ float red[4];

    float m = -3.0e38f;
    for (int j = fs + t; j < fe; j += 128) m = fmaxf(m, row[j]);
#pragma unroll
    for (int o = 16; o; o >>= 1) m = fmaxf(m, __shfl_xor_sync(0xffffffffu, m, o));
    if ((t & 31) == 0) red[t >> 5] = m;
    __syncthreads();
    m = fmaxf(fmaxf(red[0], red[1]), fmaxf(red[2], red[3]));
    __syncthreads();

    float s = 0.f;
    for (int j = fs + t; j < fe; j += 128) s += expf(row[j] - m);
#pragma unroll
    for (int o = 16; o; o >>= 1) s += __shfl_xor_sync(0xffffffffu, s, o);
    if ((t & 31) == 0) red[t >> 5] = s;
    __syncthreads();
    float inv = 1.f / (red[0] + red[1] + red[2] + red[3]);

    for (int j = fs + t; j < fe; j += 128) row[j] = expf(row[j] - m) * inv;
}

// =====================================================================
// context: ctx[NX,256] = attn(band fp32) @ value(bf16 pre-split).
// A: ldg+split register pipeline; B: cp.async. Double buffered.
// =====================================================================
__global__ __launch_bounds__(256) void context_tc(
    const float* __restrict__ attn, float* __restrict__ ctx,
    const int* __restrict__ xb)
{
    extern __shared__ __align__(16) __nv_bfloat16 dsm[];
    const int tid = threadIdx.x, lane = tid & 31, wid = tid >> 5, wm = wid >> 1, wn = wid & 1;
    const int m0 = blockIdx.y * 128, n0 = blockIdx.x * 64;

    const int g0 = xb[m0], g1 = xb[m0 + 127];
    const int kbeg = g_foff[g0] & ~31;
    const int kend = g_foff[g1 + 1];
    const int nst = (kend - kbeg + 31) >> 5;

    float4 areg[4];
    auto ldgA = [&](int k0) {
#pragma unroll
        for (int i = 0; i < 4; i++) {
            int idx = tid + i * 256, r = idx >> 3, c4 = (idx & 7) << 2;
            areg[i] = *(const float4*)(attn + (size_t)(m0 + r) * NF + k0 + c4);
        }
    };
    auto stsA = [&](int s) {
        __nv_bfloat16* bs = dsm + s * STG;
#pragma unroll
        for (int i = 0; i < 4; i++) {
            int idx = tid + i * 256, r = idx >> 3, c4 = (idx & 7) << 2;
            uint2 h, l; split4(areg[i], h, l);
            *(uint2*)(bs + r * 40 + c4) = h;
            *(uint2*)(bs + AE + r * 40 + c4) = l;
        }
    };
    auto cpaB = [&](int k0, int s) {
        __nv_bfloat16* bs = dsm + s * STG + 2 * AE;
        int r = tid >> 3, c8 = (tid & 7) * 8;
        cpa16(bs + r * 72 + c8, g_vh + (size_t)(k0 + r) * OUT_SIZE + n0 + c8);
        cpa16(bs + BE + r * 72 + c8, g_vl + (size_t)(k0 + r) * OUT_SIZE + n0 + c8);
        CPA_COMMIT;
    };

    float acc[2][4][4] = {};
    const unsigned smB = su(dsm);

    auto compute = [&](int s) {
        unsigned aB = smB + 2 * (s * STG);
        unsigned alB = aB + 2 * AE;
        unsigned bB = aB + 2 * (2 * AE);
        unsigned blB = bB + 2 * BE;
#pragma unroll
        for (int ks = 0; ks < 32; ks += 16) {
            unsigned ah[2][4], al[2][4], bh[2][4], bl[2][4];
#pragma unroll
            for (int mf = 0; mf < 2; mf++) {
                unsigned off = 2u * ((wm * 32 + mf * 16 + (lane & 15)) * 40 + ks + ((lane >> 4) << 3));
                ldsm4(ah[mf], aB + off);
                ldsm4(al[mf], alB + off);
            }
#pragma unroll
            for (int p = 0; p < 2; p++) {
                unsigned off = 2u * ((ks + (lane & 15)) * 72 + wn * 32 + p * 16 + ((lane >> 4) << 3));
                ldsm4t(bh[p], bB + off);
                ldsm4t(bl[p], blB + off);
            }
#pragma unroll
            for (int mf = 0; mf < 2; mf++)
#pragma unroll
                for (int nf = 0; nf < 4; nf++) {
                    unsigned b0 = bh[nf >> 1][(nf & 1) * 2], b1 = bh[nf >> 1][(nf & 1) * 2 + 1];
                    unsigned c0 = bl[nf >> 1][(nf & 1) * 2], c1 = bl[nf >> 1][(nf & 1) * 2 + 1];
                    mma_bf(acc[mf][nf], ah[mf], b0, b1);
                    mma_bf(acc[mf][nf], al[mf], b0, b1);
                    mma_bf(acc[mf][nf], ah[mf], c0, c1);
                }
        }
    };

    ldgA(kbeg);
    stsA(0);
    cpaB(kbeg, 0);
    for (int t = 0; t < nst; t++) {
        int s = t & 1;
        bool more = (t + 1 < nst);
        if (more) { ldgA(kbeg + (t + 1) * 32); cpaB(kbeg + (t + 1) * 32, s ^ 1); CPA_WAIT1; }
        else { CPA_WAIT0; }
        __syncthreads();
        compute(s);
        __syncthreads();
        if (more) stsA(s ^ 1);
    }

#pragma unroll
    for (int mf = 0; mf < 2; mf++)
#pragma unroll
        for (int nf = 0; nf < 4; nf++) {
            int row = m0 + wm * 32 + mf * 16 + (lane >> 2);
            int col = n0 + wn * 32 + nf * 8 + ((lane & 3) << 1);
            *(float2*)(ctx + (size_t)row * OUT_SIZE + col) = make_float2(acc[mf][nf][0], acc[mf][nf][1]);
            *(float2*)(ctx + (size_t)(row + 8) * OUT_SIZE + col) = make_float2(acc[mf][nf][2], acc[mf][nf][3]);
        }
}

// ---------------- side stream for overlapped zero-fill ----------------
struct Aux {
    cudaStream_t s = nullptr;
    cudaEvent_t e0 = nullptr, e1 = nullptr;
    Aux() {
        if (cudaStreamCreateWithFlags(&s, cudaStreamNonBlocking) != cudaSuccess) { s = nullptr; return; }
        if (cudaEventCreateWithFlags(&e0, cudaEventDisableTiming) != cudaSuccess ||
            cudaEventCreateWithFlags(&e1, cudaEventDisableTiming) != cudaSuccess) { s = nullptr; }
    }
};
static Aux g_aux;

// ---------------- launch ----------------
extern "C" void kernel_launch(void* const* d_in, const int* in_sizes, int n_in,
                              void* d_out, int out_size)
{
    const float* f       = (const float*)d_in[0];
    const float* h       = (const float*)d_in[2];
    const int*   f_batch = (const int*)  d_in[5];
    const int*   x_batch = (const int*)  d_in[6];
    const float* W_h     = (const float*)d_in[8];
    const float* W_key   = (const float*)d_in[9];
    const float* W_value = (const float*)d_in[10];

    float* out  = (float*)d_out;
    float* ctx  = out;
    float* attn = out + (size_t)NX * OUT_SIZE;

    __nv_bfloat16 *fh, *fl, *hh, *hl, *wh, *wl;
    cudaGetSymbolAddress((void**)&fh, g_fh); cudaGetSymbolAddress((void**)&fl, g_fl);
    cudaGetSymbolAddress((void**)&hh, g_hh); cudaGetSymbolAddress((void**)&hl, g_hl);
    cudaGetSymbolAddress((void**)&wh, g_wh); cudaGetSymbolAddress((void**)&wl, g_wl);

    cudaFuncSetAttribute(proj_tc,    cudaFuncAttributeMaxDynamicSharedMemorySize, PROJ_SMEM);
    cudaFuncSetAttribute(scores_tc,  cudaFuncAttributeMaxDynamicSharedMemorySize, SC_SMEM);
    cudaFuncSetAttribute(context_tc, cudaFuncAttributeMaxDynamicSharedMemorySize, PROJ_SMEM);

    bool forked = (g_aux.s != nullptr);
    if (forked) {
        cudaEventRecord(g_aux.e0, 0);
        cudaStreamWaitEvent(g_aux.s, g_aux.e0, 0);
        zero_attn<<<4096, 256, 0, g_aux.s>>>((float4*)attn, (size_t)NX * NF / 4);
        cudaEventRecord(g_aux.e1, g_aux.s);
    }

    offsets_kernel<<<1, 32>>>(f_batch);
    split_arr<<<1024, 256>>>((const float4*)f, fh, fl, NF * F_SIZE / 4);
    split_arr<<<512, 256>>>((const float4*)h, hh, hl, NX * OUT_SIZE / 4);
    split_arr<<<32, 256>>>((const float4*)W_h,     wh + WOFF_Q, wl + WOFF_Q, 256 * 128 / 4);
    split_arr<<<64, 256>>>((const float4*)W_key,   wh + WOFF_K, wl + WOFF_K, 512 * 128 / 4);
    split_arr<<<128, 256>>>((const float4*)W_value, wh + WOFF_V, wl + WOFF_V, 512 * 256 / 4);

    proj_tc<<<512, 256, PROJ_SMEM>>>();

    if (forked) cudaStreamWaitEvent(0, g_aux.e1, 0);
    else zero_attn<<<4096, 256>>>((float4*)attn, (size_t)NX * NF / 4);

    scores_tc<<<dim3(8, NX / 128), 256, SC_SMEM>>>(x_batch, attn);
    softmax_kernel<<<NX, 128>>>(attn, x_batch);
    context_tc<<<dim3(OUT_SIZE / 64, NX / 128), 256, PROJ_SMEM>>>(attn, ctx, x_batch);
}

// round 5
// speedup vs baseline: 2.3520x; 1.0285x over previous
#include <cuda_runtime.h>
#include <cuda_bf16.h>
#include <cstdint>

#define NX 8192
#define NF 8192
#define F_SIZE 512
#define OUT_SIZE 256
#define D_ATT 128
#define N_GRAPHS 16

// ---------------- scratch ----------------
__device__ int g_foff[N_GRAPHS + 1];
__device__ __nv_bfloat16 g_fh[NF * F_SIZE],  g_fl[NF * F_SIZE];
__device__ __nv_bfloat16 g_hh[NX * OUT_SIZE], g_hl[NX * OUT_SIZE];
__device__ __nv_bfloat16 g_qh[NX * D_ATT],   g_ql[NX * D_ATT];
__device__ __nv_bfloat16 g_kh[NF * D_ATT],   g_kl[NF * D_ATT];
__device__ __nv_bfloat16 g_vh[NF * OUT_SIZE], g_vl[NF * OUT_SIZE];
#define W_TOT (256 * 128 + 512 * 128 + 512 * 256)
__device__ __nv_bfloat16 g_wh[W_TOT], g_wl[W_TOT];
#define WOFF_Q 0
#define WOFF_K 32768
#define WOFF_V 98304

__global__ void offsets_kernel(const int* __restrict__ f_batch) {
    int g = threadIdx.x;
    if (g > N_GRAPHS) return;
    int lo = 0, hi = NF;
    while (lo < hi) { int mid = (lo + hi) >> 1; if (f_batch[mid] < g) lo = mid + 1; else hi = mid; }
    g_foff[g] = lo;
}

// ---------------- helpers ----------------
__device__ __forceinline__ unsigned su(const void* p) { return (unsigned)__cvta_generic_to_shared(p); }
__device__ __forceinline__ void cpa16(void* dst, const void* src) {
    asm volatile("cp.async.cg.shared.global [%0],[%1],16;\n" :: "r"(su(dst)), "l"(src));
}
#define CPA_COMMIT asm volatile("cp.async.commit_group;\n")
#define CPA_WAIT1  asm volatile("cp.async.wait_group 1;\n")
#define CPA_WAIT0  asm volatile("cp.async.wait_group 0;\n")

__device__ __forceinline__ void ldsm4(unsigned r[4], unsigned a) {
    asm volatile("ldmatrix.sync.aligned.m8n8.x4.shared.b16 {%0,%1,%2,%3},[%4];"
        : "=r"(r[0]), "=r"(r[1]), "=r"(r[2]), "=r"(r[3]) : "r"(a));
}
__device__ __forceinline__ void ldsm4t(unsigned r[4], unsigned a) {
    asm volatile("ldmatrix.sync.aligned.m8n8.x4.trans.shared.b16 {%0,%1,%2,%3},[%4];"
        : "=r"(r[0]), "=r"(r[1]), "=r"(r[2]), "=r"(r[3]) : "r"(a));
}
__device__ __forceinline__ void mma_bf(float d[4], const unsigned a[4], unsigned b0, unsigned b1) {
    asm volatile("mma.sync.aligned.m16n8k16.row.col.f32.bf16.bf16.f32 "
        "{%0,%1,%2,%3},{%4,%5,%6,%7},{%8,%9},{%0,%1,%2,%3};"
        : "+f"(d[0]), "+f"(d[1]), "+f"(d[2]), "+f"(d[3])
        : "r"(a[0]), "r"(a[1]), "r"(a[2]), "r"(a[3]), "r"(b0), "r"(b1));
}
__device__ __forceinline__ unsigned pk2(__nv_bfloat16 a, __nv_bfloat16 b) {
    __nv_bfloat162 t(a, b); return *reinterpret_cast<unsigned*>(&t);
}
__device__ __forceinline__ void split4(float4 v, uint2& hi, uint2& lo) {
    __nv_bfloat16 h0 = __float2bfloat16_rn(v.x), h1 = __float2bfloat16_rn(v.y);
    __nv_bfloat16 h2 = __float2bfloat16_rn(v.z), h3 = __float2bfloat16_rn(v.w);
    __nv_bfloat16 l0 = __float2bfloat16_rn(v.x - __bfloat162float(h0));
    __nv_bfloat16 l1 = __float2bfloat16_rn(v.y - __bfloat162float(h1));
    __nv_bfloat16 l2 = __float2bfloat16_rn(v.z - __bfloat162float(h2));
    __nv_bfloat16 l3 = __float2bfloat16_rn(v.w - __bfloat162float(h3));
    hi.x = pk2(h0, h1); hi.y = pk2(h2, h3);
    lo.x = pk2(l0, l1); lo.y = pk2(l2, l3);
}
__device__ __forceinline__ void split2w(float x, float y, unsigned& h, unsigned& l) {
    __nv_bfloat16 hx = __float2bfloat16_rn(x), hy = __float2bfloat16_rn(y);
    h = pk2(hx, hy);
    l = pk2(__float2bfloat16_rn(x - __bfloat162float(hx)),
            __float2bfloat16_rn(y - __bfloat162float(hy)));
}

// ---------------- fused fp32 -> bf16 hi/lo for all 5 inputs ----------------
#define SEG0 1048576            // f   (NF*F_SIZE/4)
#define SEG1 (SEG0 + 524288)    // h
#define SEG2 (SEG1 + 8192)      // W_h
#define SEG3 (SEG2 + 16384)     // W_key
#define SEG4 (SEG3 + 32768)     // W_value
__global__ void split_all(const float4* __restrict__ f, const float4* __restrict__ h,
                          const float4* __restrict__ Wh, const float4* __restrict__ Wk,
                          const float4* __restrict__ Wv) {
    int i = blockIdx.x * blockDim.x + threadIdx.x;
    int s = gridDim.x * blockDim.x;
    for (; i < SEG4; i += s) {
        const float4* src; uint2 *dh, *dl; int li;
        if (i < SEG0)      { src = f;  li = i;        dh = (uint2*)g_fh; dl = (uint2*)g_fl; }
        else if (i < SEG1) { src = h;  li = i - SEG0; dh = (uint2*)g_hh; dl = (uint2*)g_hl; }
        else if (i < SEG2) { src = Wh; li = i - SEG1; dh = (uint2*)(g_wh + WOFF_Q); dl = (uint2*)(g_wl + WOFF_Q); }
        else if (i < SEG3) { src = Wk; li = i - SEG2; dh = (uint2*)(g_wh + WOFF_K); dl = (uint2*)(g_wl + WOFF_K); }
        else               { src = Wv; li = i - SEG3; dh = (uint2*)(g_wh + WOFF_V); dl = (uint2*)(g_wl + WOFF_V); }
        uint2 hh, ll; split4(src[li], hh, ll);
        dh[li] = hh; dl[li] = ll;
    }
}

// ---------------- zero only the band complement (disjoint from scores) ----------------
__global__ __launch_bounds__(256) void zero_nonband(
    float* __restrict__ attn, const int* __restrict__ xb)
{
    const int row = blockIdx.x;
    const int m0 = row & ~127;
    const int zs = g_foff[xb[m0]] & ~63;
    const int ze = min(NF, (g_foff[xb[m0 + 127] + 1] + 63) & ~63);
    float4* p = (float4*)(attn + (size_t)row * NF);
    const float4 z = make_float4(0.f, 0.f, 0.f, 0.f);
    const int t = threadIdx.x;
    for (int i = t; i < (zs >> 2); i += 256) p[i] = z;
    for (int i = (ze >> 2) + t; i < (NF >> 2); i += 256) p[i] = z;
}

// =====================================================================
// projections (bf16 hi/lo in, bf16 hi/lo out), cp.async double buffer.
// b(+base): [0,128) q, [128,256) k, [256,512) v.
// =====================================================================
#define AE 5120
#define BE 2304
#define STG (2 * AE + 2 * BE)
#define PROJ_SMEM (2 * STG * 2)

__global__ __launch_bounds__(256) void proj_tc(int base) {
    extern __shared__ __align__(16) __nv_bfloat16 dsm[];
    const int tid = threadIdx.x, lane = tid & 31, wid = tid >> 5, wm = wid >> 1, wn = wid & 1;
    const int b = blockIdx.x + base;

    const __nv_bfloat16 *Agh, *Agl, *Bgh, *Bgl;
    __nv_bfloat16 *Coh, *Col;
    int lda, ldb, ldc, K, m0, n0;
    if (b < 128) {
        Agh = g_hh; Agl = g_hl; lda = OUT_SIZE; K = OUT_SIZE;
        Bgh = g_wh + WOFF_Q; Bgl = g_wl + WOFF_Q; ldb = D_ATT; ldc = D_ATT;
        Coh = g_qh; Col = g_ql; m0 = (b >> 1) * 128; n0 = (b & 1) * 64;
    } else if (b < 256) {
        int lb = b - 128;
        Agh = g_fh; Agl = g_fl; lda = F_SIZE; K = F_SIZE;
        Bgh = g_wh + WOFF_K; Bgl = g_wl + WOFF_K; ldb = D_ATT; ldc = D_ATT;
        Coh = g_kh; Col = g_kl; m0 = (lb >> 1) * 128; n0 = (lb & 1) * 64;
    } else {
        int lb = b - 256;
        Agh = g_fh; Agl = g_fl; lda = F_SIZE; K = F_SIZE;
        Bgh = g_wh + WOFF_V; Bgl = g_wl + WOFF_V; ldb = OUT_SIZE; ldc = OUT_SIZE;
        Coh = g_vh; Col = g_vl; m0 = (lb >> 2) * 128; n0 = (lb & 3) * 64;
    }

    auto pf = [&](int k0, int s) {
        __nv_bfloat16* bs = dsm + s * STG;
#pragma unroll
        for (int i = 0; i < 2; i++) {
            int idx = tid + i * 256, r = idx >> 2, c8 = (idx & 3) * 8;
            cpa16(bs + r * 40 + c8, Agh + (size_t)(m0 + r) * lda + k0 + c8);
            cpa16(bs + AE + r * 40 + c8, Agl + (size_t)(m0 + r) * lda + k0 + c8);
        }
        {
            int r = tid >> 3, c8 = (tid & 7) * 8;
            cpa16(bs + 2 * AE + r * 72 + c8, Bgh + (size_t)(k0 + r) * ldb + n0 + c8);
            cpa16(bs + 2 * AE + BE + r * 72 + c8, Bgl + (size_t)(k0 + r) * ldb + n0 + c8);
        }
        CPA_COMMIT;
    };

    float acc[2][4][4] = {};
    const unsigned smB = su(dsm);

    auto compute = [&](int s) {
        unsigned aB = smB + 2 * (s * STG);
        unsigned alB = aB + 2 * AE;
        unsigned bB = aB + 2 * (2 * AE);
        unsigned blB = bB + 2 * BE;
#pragma unroll
        for (int ks = 0; ks < 32; ks += 16) {
            unsigned ah[2][4], al[2][4], bh[2][4], bl[2][4];
#pragma unroll
            for (int mf = 0; mf < 2; mf++) {
                unsigned off = 2u * ((wm * 32 + mf * 16 + (lane & 15)) * 40 + ks + ((lane >> 4) << 3));
                ldsm4(ah[mf], aB + off);
                ldsm4(al[mf], alB + off);
            }
#pragma unroll
            for (int p = 0; p < 2; p++) {
                unsigned off = 2u * ((ks + (lane & 15)) * 72 + wn * 32 + p * 16 + ((lane >> 4) << 3));
                ldsm4t(bh[p], bB + off);
                ldsm4t(bl[p], blB + off);
            }
#pragma unroll
            for (int mf = 0; mf < 2; mf++)
#pragma unroll
                for (int nf = 0; nf < 4; nf++) {
                    unsigned b0 = bh[nf >> 1][(nf & 1) * 2], b1 = bh[nf >> 1][(nf & 1) * 2 + 1];
                    unsigned c0 = bl[nf >> 1][(nf & 1) * 2], c1 = bl[nf >> 1][(nf & 1) * 2 + 1];
                    mma_bf(acc[mf][nf], ah[mf], b0, b1);
                    mma_bf(acc[mf][nf], al[mf], b0, b1);
                    mma_bf(acc[mf][nf], ah[mf], c0, c1);
                }
        }
    };

    const int nst = K / 32;
    pf(0, 0);
    for (int t = 0; t < nst; t++) {
        int s = t & 1;
        if (t + 1 < nst) { pf((t + 1) * 32, s ^ 1); CPA_WAIT1; } else { CPA_WAIT0; }
        __syncthreads();
        compute(s);
        __syncthreads();
    }

#pragma unroll
    for (int mf = 0; mf < 2; mf++)
#pragma unroll
        for (int nf = 0; nf < 4; nf++) {
            int row = m0 + wm * 32 + mf * 16 + (lane >> 2);
            int col = n0 + wn * 32 + nf * 8 + ((lane & 3) << 1);
            unsigned h0, l0, h1, l1;
            split2w(acc[mf][nf][0], acc[mf][nf][1], h0, l0);
            split2w(acc[mf][nf][2], acc[mf][nf][3], h1, l1);
            *(unsigned*)(Coh + (size_t)row * ldc + col) = h0;
            *(unsigned*)(Col + (size_t)row * ldc + col) = l0;
            *(unsigned*)(Coh + (size_t)(row + 8) * ldc + col) = h1;
            *(unsigned*)(Col + (size_t)(row + 8) * ldc + col) = l1;
        }
}

// =====================================================================
// scores: band tiles, bf16 pre-split inputs, writes cols [zs,ze) per block.
// =====================================================================
#define QLD 136
#define QE (128 * QLD)
#define KE (64 * QLD)
#define SC_SMEM ((2 * QE + 2 * KE) * 2)

__global__ __launch_bounds__(256) void scores_tc(
    const int* __restrict__ xb, float* __restrict__ attn)
{
    extern __shared__ __align__(16) __nv_bfloat16 dsm[];
    __nv_bfloat16* Qh = dsm;
    __nv_bfloat16* Ql = Qh + QE;
    __nv_bfloat16* Kh = Ql + QE;
    __nv_bfloat16* Kl = Kh + KE;

    const int tid = threadIdx.x, lane = tid & 31, wid = tid >> 5, wm = wid >> 1, wn = wid & 1;
    const int m0 = blockIdx.y * 128;

    const int jmin = g_foff[xb[m0]];
    const int jmax = g_foff[xb[m0 + 127] + 1];
    const int jt_lo = jmin >> 6, jt_hi = (jmax + 63) >> 6;
    if (jt_lo + (int)blockIdx.x >= jt_hi) return;

    int fs[2][2], fe[2][2];
#pragma unroll
    for (int mf = 0; mf < 2; mf++)
#pragma unroll
        for (int hh = 0; hh < 2; hh++) {
            int row = m0 + wm * 32 + mf * 16 + (lane >> 2) + hh * 8;
            int g = xb[row];
            fs[mf][hh] = g_foff[g]; fe[mf][hh] = g_foff[g + 1];
        }

#pragma unroll
    for (int i = 0; i < 8; i++) {
        int idx = tid + i * 256, r = idx >> 4, c8 = (idx & 15) * 8;
        cpa16(Qh + r * QLD + c8, g_qh + (size_t)(m0 + r) * D_ATT + c8);
        cpa16(Ql + r * QLD + c8, g_ql + (size_t)(m0 + r) * D_ATT + c8);
    }
    CPA_COMMIT;

    const unsigned qhB = su(Qh), qlB = su(Ql), khB = su(Kh), klB = su(Kl);

    for (int jt = jt_lo + blockIdx.x; jt < jt_hi; jt += 8) {
        const int j0 = jt << 6;
#pragma unroll
        for (int i = 0; i < 4; i++) {
            int idx = tid + i * 256, r = idx >> 4, c8 = (idx & 15) * 8;
            cpa16(Kh + r * QLD + c8, g_kh + (size_t)(j0 + r) * D_ATT + c8);
            cpa16(Kl + r * QLD + c8, g_kl + (size_t)(j0 + r) * D_ATT + c8);
        }
        CPA_COMMIT;
        CPA_WAIT0;
        __syncthreads();

        float acc[2][4][4] = {};
#pragma unroll
        for (int d0 = 0; d0 < D_ATT; d0 += 16) {
            unsigned ah[2][4], al[2][4], bh[2][4], bl[2][4];
#pragma unroll
            for (int mf = 0; mf < 2; mf++) {
                unsigned off = 2u * ((wm * 32 + mf * 16 + (lane & 15)) * QLD + d0 + ((lane >> 4) << 3));
                ldsm4(ah[mf], qhB + off);
                ldsm4(al[mf], qlB + off);
            }
#pragma unroll
            for (int p = 0; p < 2; p++) {
                unsigned off = 2u * ((wn * 32 + p * 16 + ((lane >> 4) << 3) + (lane & 7)) * QLD + d0 + (lane & 8));
                ldsm4(bh[p], khB + off);
                ldsm4(bl[p], klB + off);
            }
#pragma unroll
            for (int mf = 0; mf < 2; mf++)
#pragma unroll
                for (int nf = 0; nf < 4; nf++) {
                    unsigned b0 = bh[nf >> 1][(nf & 1) * 2], b1 = bh[nf >> 1][(nf & 1) * 2 + 1];
                    unsigned c0 = bl[nf >> 1][(nf & 1) * 2], c1 = bl[nf >> 1][(nf & 1) * 2 + 1];
                    mma_bf(acc[mf][nf], ah[mf], b0, b1);
                    mma_bf(acc[mf][nf], al[mf], b0, b1);
                    mma_bf(acc[mf][nf], ah[mf], c0, c1);
                }
        }
        __syncthreads();

#pragma unroll
        for (int mf = 0; mf < 2; mf++) {
            int row = m0 + wm * 32 + mf * 16 + (lane >> 2);
#pragma unroll
            for (int nf = 0; nf < 4; nf++) {
                int col = j0 + wn * 32 + nf * 8 + ((lane & 3) << 1);
                float2 w0, w1;
                w0.x = (col >= fs[mf][0] && col < fe[mf][0])         ? acc[mf][nf][0] : 0.f;
                w0.y = (col + 1 >= fs[mf][0] && col + 1 < fe[mf][0]) ? acc[mf][nf][1] : 0.f;
                w1.x = (col >= fs[mf][1] && col < fe[mf][1])         ? acc[mf][nf][2] : 0.f;
                w1.y = (col + 1 >= fs[mf][1] && col + 1 < fe[mf][1]) ? acc[mf][nf][3] : 0.f;
                *(float2*)(attn + (size_t)row * NF + col) = w0;
                *(float2*)(attn + (size_t)(row + 8) * NF + col) = w1;
            }
        }
    }
}

// =====================================================================
// softmax: online single-pass (max,sum), then normalize. 2 reads + 1 write.
// =====================================================================
__global__ __launch_bounds__(128) void softmax_kernel(
    float* __restrict__ attn, const int* __restrict__ xb)
{
    const int i = blockIdx.x, t = threadIdx.x;
    const int g = xb[i], fs = g_foff[g], fe = g_foff[g + 1];
    float* row = attn + (size_t)i * NF;
    __shared__ float redm[4], reds[4];

    float m = -3.0e38f, s = 0.f;
    for (int j = fs + t; j < fe; j += 128) {
        float v = row[j];
        float mn = fmaxf(m, v);
        s = s * __expf(m - mn) + __expf(v - mn);
        m = mn;
    }
#pragma unroll
    for (int o = 16; o; o >>= 1) {
        float m2 = __shfl_xor_sync(0xffffffffu, m, o);
        float s2 = __shfl_xor_sync(0xffffffffu, s, o);
        float mn = fmaxf(m, m2);
        s = s * __expf(m - mn) + s2 * __expf(m2 - mn);
        m = mn;
    }
    if ((t & 31) == 0) { redm[t >> 5] = m; reds[t >> 5] = s; }
    __syncthreads();
    float mt = fmaxf(fmaxf(redm[0], redm[1]), fmaxf(redm[2], redm[3]));
    float st = reds[0] * __expf(redm[0] - mt) + reds[1] * __expf(redm[1] - mt)
             + reds[2] * __expf(redm[2] - mt) + reds[3] * __expf(redm[3] - mt);
    float inv = 1.f / st;

    for (int j = fs + t; j < fe; j += 128) row[j] = __expf(row[j] - mt) * inv;
}

// =====================================================================
// context: attn(band fp32) @ value(bf16 pre-split)
// =====================================================================
__global__ __launch_bounds__(256) void context_tc(
    const float* __restrict__ attn, float* __restrict__ ctx,
    const int* __restrict__ xb)
{
    extern __shared__ __align__(16) __nv_bfloat16 dsm[];
    const int tid = threadIdx.x, lane = tid & 31, wid = tid >> 5, wm = wid >> 1, wn = wid & 1;
    const int m0 = blockIdx.y * 128, n0 = blockIdx.x * 64;

    const int g0 = xb[m0], g1 = xb[m0 + 127];
    const int kbeg = g_foff[g0] & ~31;
    const int kend = g_foff[g1 + 1];
    const int nst = (kend - kbeg + 31) >> 5;

    float4 areg[4];
    auto ldgA = [&](int k0) {
#pragma unroll
        for (int i = 0; i < 4; i++) {
            int idx = tid + i * 256, r = idx >> 3, c4 = (idx & 7) << 2;
            areg[i] = *(const float4*)(attn + (size_t)(m0 + r) * NF + k0 + c4);
        }
    };
    auto stsA = [&](int s) {
        __nv_bfloat16* bs = dsm + s * STG;
#pragma unroll
        for (int i = 0; i < 4; i++) {
            int idx = tid + i * 256, r = idx >> 3, c4 = (idx & 7) << 2;
            uint2 h, l; split4(areg[i], h, l);
            *(uint2*)(bs + r * 40 + c4) = h;
            *(uint2*)(bs + AE + r * 40 + c4) = l;
        }
    };
    auto cpaB = [&](int k0, int s) {
        __nv_bfloat16* bs = dsm + s * STG + 2 * AE;
        int r = tid >> 3, c8 = (tid & 7) * 8;
        cpa16(bs + r * 72 + c8, g_vh + (size_t)(k0 + r) * OUT_SIZE + n0 + c8);
        cpa16(bs + BE + r * 72 + c8, g_vl + (size_t)(k0 + r) * OUT_SIZE + n0 + c8);
        CPA_COMMIT;
    };

    float acc[2][4][4] = {};
    const unsigned smB = su(dsm);

    auto compute = [&](int s) {
        unsigned aB = smB + 2 * (s * STG);
        unsigned alB = aB + 2 * AE;
        unsigned bB = aB + 2 * (2 * AE);
        unsigned blB = bB + 2 * BE;
#pragma unroll
        for (int ks = 0; ks < 32; ks += 16) {
            unsigned ah[2][4], al[2][4], bh[2][4], bl[2][4];
#pragma unroll
            for (int mf = 0; mf < 2; mf++) {
                unsigned off = 2u * ((wm * 32 + mf * 16 + (lane & 15)) * 40 + ks + ((lane >> 4) << 3));
                ldsm4(ah[mf], aB + off);
                ldsm4(al[mf], alB + off);
            }
#pragma unroll
            for (int p = 0; p < 2; p++) {
                unsigned off = 2u * ((ks + (lane & 15)) * 72 + wn * 32 + p * 16 + ((lane >> 4) << 3));
                ldsm4t(bh[p], bB + off);
                ldsm4t(bl[p], blB + off);
            }
#pragma unroll
            for (int mf = 0; mf < 2; mf++)
#pragma unroll
                for (int nf = 0; nf < 4; nf++) {
                    unsigned b0 = bh[nf >> 1][(nf & 1) * 2], b1 = bh[nf >> 1][(nf & 1) * 2 + 1];
                    unsigned c0 = bl[nf >> 1][(nf & 1) * 2], c1 = bl[nf >> 1][(nf & 1) * 2 + 1];
                    mma_bf(acc[mf][nf], ah[mf], b0, b1);
                    mma_bf(acc[mf][nf], al[mf], b0, b1);
                    mma_bf(acc[mf][nf], ah[mf], c0, c1);
                }
        }
    };

    ldgA(kbeg);
    stsA(0);
    cpaB(kbeg, 0);
    for (int t = 0; t < nst; t++) {
        int s = t & 1;
        bool more = (t + 1 < nst);
        if (more) { ldgA(kbeg + (t + 1) * 32); cpaB(kbeg + (t + 1) * 32, s ^ 1); CPA_WAIT1; }
        else { CPA_WAIT0; }
        __syncthreads();
        compute(s);
        __syncthreads();
        if (more) stsA(s ^ 1);
    }

#pragma unroll
    for (int mf = 0; mf < 2; mf++)
#pragma unroll
        for (int nf = 0; nf < 4; nf++) {
            int row = m0 + wm * 32 + mf * 16 + (lane >> 2);
            int col = n0 + wn * 32 + nf * 8 + ((lane & 3) << 1);
            *(float2*)(ctx + (size_t)row * OUT_SIZE + col) = make_float2(acc[mf][nf][0], acc[mf][nf][1]);
            *(float2*)(ctx + (size_t)(row + 8) * OUT_SIZE + col) = make_float2(acc[mf][nf][2], acc[mf][nf][3]);
        }
}

// ---------------- side streams ----------------
struct Aux {
    cudaStream_t s1 = nullptr, s2 = nullptr;
    cudaEvent_t eOff = nullptr, eSplit = nullptr, eZero = nullptr, eV = nullptr;
    bool ok = false;
    Aux() {
        if (cudaStreamCreateWithFlags(&s1, cudaStreamNonBlocking) != cudaSuccess) return;
        if (cudaStreamCreateWithFlags(&s2, cudaStreamNonBlocking) != cudaSuccess) return;
        if (cudaEventCreateWithFlags(&eOff, cudaEventDisableTiming) != cudaSuccess) return;
        if (cudaEventCreateWithFlags(&eSplit, cudaEventDisableTiming) != cudaSuccess) return;
        if (cudaEventCreateWithFlags(&eZero, cudaEventDisableTiming) != cudaSuccess) return;
        if (cudaEventCreateWithFlags(&eV, cudaEventDisableTiming) != cudaSuccess) return;
        ok = true;
    }
};
static Aux g_aux;

// ---------------- launch ----------------
extern "C" void kernel_launch(void* const* d_in, const int* in_sizes, int n_in,
                              void* d_out, int out_size)
{
    const float* f       = (const float*)d_in[0];
    const float* h       = (const float*)d_in[2];
    const int*   f_batch = (const int*)  d_in[5];
    const int*   x_batch = (const int*)  d_in[6];
    const float* W_h     = (const float*)d_in[8];
    const float* W_key   = (const float*)d_in[9];
    const float* W_value = (const float*)d_in[10];

    float* out  = (float*)d_out;
    float* ctx  = out;
    float* attn = out + (size_t)NX * OUT_SIZE;

    cudaFuncSetAttribute(proj_tc,    cudaFuncAttributeMaxDynamicSharedMemorySize, PROJ_SMEM);
    cudaFuncSetAttribute(scores_tc,  cudaFuncAttributeMaxDynamicSharedMemorySize, SC_SMEM);
    cudaFuncSetAttribute(context_tc, cudaFuncAttributeMaxDynamicSharedMemorySize, PROJ_SMEM);

    offsets_kernel<<<1, 32>>>(f_batch);

    if (g_aux.ok) {
        // fork zero-fill of band complement (disjoint from all other writes)
        cudaEventRecord(g_aux.eOff, 0);
        cudaStreamWaitEvent(g_aux.s1, g_aux.eOff, 0);
        zero_nonband<<<NX, 256, 0, g_aux.s1>>>(attn, x_batch);
        cudaEventRecord(g_aux.eZero, g_aux.s1);

        split_all<<<2048, 256>>>((const float4*)f, (const float4*)h,
                                 (const float4*)W_h, (const float4*)W_key, (const float4*)W_value);
        cudaEventRecord(g_aux.eSplit, 0);

        // V projection forked; only context needs it
        cudaStreamWaitEvent(g_aux.s2, g_aux.eSplit, 0);
        proj_tc<<<256, 256, PROJ_SMEM, g_aux.s2>>>(256);
        cudaEventRecord(g_aux.eV, g_aux.s2);

        proj_tc<<<256, 256, PROJ_SMEM>>>(0);   // Q + K
        scores_tc<<<dim3(8, NX / 128), 256, SC_SMEM>>>(x_batch, attn);
        softmax_kernel<<<NX, 128>>>(attn, x_batch);

        cudaStreamWaitEvent(0, g_aux.eV, 0);
        context_tc<<<dim3(OUT_SIZE / 64, NX / 128), 256, PROJ_SMEM>>>(attn, ctx, x_batch);
        cudaStreamWaitEvent(0, g_aux.eZero, 0);  // join forked stream for capture
    } else {
        zero_nonband<<<NX, 256>>>(attn, x_batch);
        split_all<<<2048, 256>>>((const float4*)f, (const float4*)h,
                                 (const float4*)W_h, (const float4*)W_key, (const float4*)W_value);
        proj_tc<<<256, 256, PROJ_SMEM>>>(0);
        proj_tc<<<256, 256, PROJ_SMEM>>>(256);
        scores_tc<<<dim3(8, NX / 128), 256, SC_SMEM>>>(x_batch, attn);
        softmax_kernel<<<NX, 128>>>(attn, x_batch);
        context_tc<<<dim3(OUT_SIZE / 64, NX / 128), 256, PROJ_SMEM>>>(attn, ctx, x_batch);
    }
}